// round 16
// baseline (speedup 1.0000x reference)
#include <cuda_runtime.h>
#include <cuda_bf16.h>
#include <cstdint>

// ============================================================================
// LinkPrediction, factored:
//   U = relu(x)@W1[0:128] + b1   (per node)     V = relu(x)@W1[128:256]
//   out[e] = relu(U[e0]+V[e1]) @ W2 + b2        (per edge, memory-bound)
// GEMM via warp-level bf16 hi/lo 3-term mma.sync (plain sm_103 compatible).
// ============================================================================

constexpr int NODES_MAX = 100352;          // 784 * 128
constexpr int KH   = 128;                  // feature dim
constexpr int NOUT = 1024;                 // 512 (U) + 512 (V) columns
constexpr int KPAD = 136;                  // padded k stride (bf16 elems) -> conflict-free ldmatrix

__device__ __nv_bfloat16 g_bp_hi[NOUT * KH];   // B' [n'][k] hi  (n'<512 -> W1_top^T, else W1_bot^T)
__device__ __nv_bfloat16 g_bp_lo[NOUT * KH];
__device__ float g_U[(size_t)NODES_MAX * 512];
__device__ float g_V[(size_t)NODES_MAX * 512];
__device__ int g_edges_is_i32;

// SMEM (bytes) for uv_gemm
constexpr int SA_HI = 0;                        // A hi [128][136] bf16 = 34816
constexpr int SA_LO = 34816;
constexpr int SB    = 69632;                    // 4 x [64][136] bf16 (2 stages x hi/lo)
constexpr int SB_SZ = 64 * KPAD * 2;            // 17408
constexpr int SMEM_TOTAL = SB + 4 * SB_SZ;      // 139264

__device__ __forceinline__ uint32_t smem_u32(const void* p) {
    uint32_t a;
    asm("{ .reg .u64 t; cvta.to.shared.u64 t, %1; cvt.u32.u64 %0, t; }" : "=r"(a) : "l"(p));
    return a;
}

#define LDSM_X4(r, addr) \
    asm volatile("ldmatrix.sync.aligned.m8n8.x4.shared.b16 {%0,%1,%2,%3}, [%4];" \
        : "=r"((r)[0]), "=r"((r)[1]), "=r"((r)[2]), "=r"((r)[3]) : "r"(addr))

#define MMA_BF16(d, a, b0_, b1_) \
    asm volatile("mma.sync.aligned.m16n8k16.row.col.f32.bf16.bf16.f32 " \
        "{%0,%1,%2,%3}, {%4,%5,%6,%7}, {%8,%9}, {%0,%1,%2,%3};" \
        : "+f"((d)[0]), "+f"((d)[1]), "+f"((d)[2]), "+f"((d)[3]) \
        : "r"((a)[0]), "r"((a)[1]), "r"((a)[2]), "r"((a)[3]), "r"(b0_), "r"(b1_))

__device__ __forceinline__ uint32_t split_pack(float x0, float x1, uint32_t& lo_pack) {
    __nv_bfloat16 h0 = __float2bfloat16(x0);
    __nv_bfloat16 h1 = __float2bfloat16(x1);
    __nv_bfloat16 l0 = __float2bfloat16(x0 - __bfloat162float(h0));
    __nv_bfloat16 l1 = __float2bfloat16(x1 - __bfloat162float(h1));
    lo_pack = (uint32_t)__bfloat16_as_ushort(l0) | ((uint32_t)__bfloat16_as_ushort(l1) << 16);
    return (uint32_t)__bfloat16_as_ushort(h0) | ((uint32_t)__bfloat16_as_ushort(h1) << 16);
}

// ---- prekernels -------------------------------------------------------------
__global__ void detect_edge_dtype(const void* __restrict__ edges, int n_check,
                                  long long n_nodes) {
    __shared__ int bad;
    if (threadIdx.x == 0) bad = 0;
    __syncthreads();
    const unsigned long long* e = (const unsigned long long*)edges;
    int local = 0;
    for (int i = threadIdx.x; i < n_check; i += blockDim.x)
        if (e[i] >= (unsigned long long)n_nodes) local = 1;
    if (local) bad = 1;
    __syncthreads();
    if (threadIdx.x == 0) g_edges_is_i32 = bad;
}

// W1 [256,512] -> B' [1024][128] hi/lo:  B'[n + 512*(k>>7)][k&127] = W1[k][n]
__global__ void split_w1(const float* __restrict__ W1) {
    int idx = blockIdx.x * blockDim.x + threadIdx.x;
    if (idx < 256 * 512) {
        int k = idx >> 9, n = idx & 511;
        float x = W1[idx];
        __nv_bfloat16 h = __float2bfloat16(x);
        int np = n + ((k >> 7) << 9);
        int kp = k & 127;
        g_bp_hi[np * KH + kp] = h;
        g_bp_lo[np * KH + kp] = __float2bfloat16(x - __bfloat162float(h));
    }
}

// ---- kernel 1: U/V GEMM -------------------------------------------------------
__device__ __forceinline__ void prefetch_b(uint32_t sb, int buf, int chunk, int tid) {
    #pragma unroll
    for (int v = 0; v < 2; ++v) {
        const __nv_bfloat16* src = v ? g_bp_lo : g_bp_hi;
        const uint32_t dst0 = sb + SB + (uint32_t)(buf * 2 + v) * SB_SZ;
        #pragma unroll
        for (int i = tid; i < 1024; i += 256) {          // 64 rows x 16 segs of 16B
            const int row = i >> 4, seg = i & 15;
            const uint32_t d = dst0 + (uint32_t)row * (KPAD * 2) + seg * 16;
            const void* s = src + (size_t)(chunk * 64 + row) * KH + seg * 8;
            asm volatile("cp.async.cg.shared.global [%0], [%1], 16;" :: "r"(d), "l"(s));
        }
    }
    asm volatile("cp.async.commit_group;");
}

__global__ void __launch_bounds__(256, 1)
uv_gemm_kernel(const float* __restrict__ feat, const float* __restrict__ b1,
               int n_nodes)
{
    extern __shared__ char smem[];
    const uint32_t sb = smem_u32(smem);
    const int tid = threadIdx.x, lane = tid & 31, wid = tid >> 5;
    const int m0 = blockIdx.x * 128;

    prefetch_b(sb, 0, 0, tid);

    // ---- A: 128 node rows, relu + bf16 hi/lo split (dense, coalesced) ----
    #pragma unroll 4
    for (int it = 0; it < 16; ++it) {
        const int r = it * 8 + wid;
        int node = m0 + r;
        if (node >= n_nodes) node = n_nodes - 1;
        float4 x = __ldg(reinterpret_cast<const float4*>(feat + (size_t)node * KH) + lane);
        x.x = fmaxf(x.x, 0.f); x.y = fmaxf(x.y, 0.f);
        x.z = fmaxf(x.z, 0.f); x.w = fmaxf(x.w, 0.f);
        uint32_t l01, l23;
        const uint32_t h01 = split_pack(x.x, x.y, l01);
        const uint32_t h23 = split_pack(x.z, x.w, l23);
        const uint32_t off = (uint32_t)(r * KPAD + lane * 4) * 2;
        *reinterpret_cast<uint2*>(smem + SA_HI + off) = make_uint2(h01, h23);
        *reinterpret_cast<uint2*>(smem + SA_LO + off) = make_uint2(l01, l23);
    }

    // warp tiling: 4 x 2 warps cover 128m x 64n per chunk; each warp 32m x 32n
    const int warpM = wid & 3, warpN = wid >> 2;
    const int lr = lane & 15;                  // ldmatrix row-within-16
    const int kq = (lane >> 4) * 8;            // ldmatrix k offset 0/8
    const uint32_t a_hi0 = sb + SA_HI + (uint32_t)((warpM * 32 + lr) * KPAD + kq) * 2;
    const uint32_t a_lo0 = sb + SA_LO + (uint32_t)((warpM * 32 + lr) * KPAD + kq) * 2;

    for (int c = 0; c < 16; ++c) {
        if (c + 1 < 16) {
            prefetch_b(sb, (c + 1) & 1, c + 1, tid);
            asm volatile("cp.async.wait_group 1;" ::: "memory");
        } else {
            asm volatile("cp.async.wait_group 0;" ::: "memory");
        }
        __syncthreads();   // B[c] (and A on first iter) visible

        const uint32_t bbase = sb + SB + (uint32_t)((c & 1) * 2) * SB_SZ;
        const uint32_t b_hi0 = bbase + (uint32_t)((warpN * 32 + lr) * KPAD + kq) * 2;
        const uint32_t b_lo0 = b_hi0 + SB_SZ;

        float acc[8][4];
        #pragma unroll
        for (int j = 0; j < 8; ++j)
            acc[j][0] = acc[j][1] = acc[j][2] = acc[j][3] = 0.f;

        #pragma unroll
        for (int k = 0; k < 128; k += 16) {
            uint32_t ah0[4], ah1[4], al0[4], al1[4];
            LDSM_X4(ah0, a_hi0 + k * 2);
            LDSM_X4(ah1, a_hi0 + (16 * KPAD + k) * 2);
            LDSM_X4(al0, a_lo0 + k * 2);
            LDSM_X4(al1, a_lo0 + (16 * KPAD + k) * 2);
            #pragma unroll
            for (int jj = 0; jj < 2; ++jj) {
                uint32_t bh[4], bl[4];
                LDSM_X4(bh, b_hi0 + (jj * 16 * KPAD + k) * 2);
                LDSM_X4(bl, b_lo0 + (jj * 16 * KPAD + k) * 2);
                // 3-term hi/lo split (lo*lo dropped)
                MMA_BF16(acc[jj * 2],     ah0, bh[0], bh[2]);
                MMA_BF16(acc[jj * 2 + 1], ah0, bh[1], bh[3]);
                MMA_BF16(acc[jj * 2],     ah0, bl[0], bl[2]);
                MMA_BF16(acc[jj * 2 + 1], ah0, bl[1], bl[3]);
                MMA_BF16(acc[jj * 2],     al0, bh[0], bh[2]);
                MMA_BF16(acc[jj * 2 + 1], al0, bh[1], bh[3]);
                MMA_BF16(acc[4 + jj * 2],     ah1, bh[0], bh[2]);
                MMA_BF16(acc[4 + jj * 2 + 1], ah1, bh[1], bh[3]);
                MMA_BF16(acc[4 + jj * 2],     ah1, bl[0], bl[2]);
                MMA_BF16(acc[4 + jj * 2 + 1], ah1, bl[1], bl[3]);
                MMA_BF16(acc[4 + jj * 2],     al1, bh[0], bh[2]);
                MMA_BF16(acc[4 + jj * 2 + 1], al1, bh[1], bh[3]);
            }
        }

        // ---- store D chunk straight to U / V (b1 folded into U) ----
        #pragma unroll
        for (int i = 0; i < 2; ++i) {
            #pragma unroll
            for (int j = 0; j < 4; ++j) {
                const float* a = acc[i * 4 + j];
                const int np = c * 64 + warpN * 32 + j * 8 + (lane & 3) * 2;
                const int mA = warpM * 32 + i * 16 + (lane >> 2);
                float add0 = 0.f, add1 = 0.f;
                float* base;
                if (np < 512) {
                    add0 = __ldg(&b1[np]); add1 = __ldg(&b1[np + 1]);
                    base = g_U + np;
                } else {
                    base = g_V + (np - 512);
                }
                const int n0 = m0 + mA, n1 = n0 + 8;
                if (n0 < n_nodes)
                    *reinterpret_cast<float2*>(base + (size_t)n0 * 512) =
                        make_float2(a[0] + add0, a[1] + add1);
                if (n1 < n_nodes)
                    *reinterpret_cast<float2*>(base + (size_t)n1 * 512) =
                        make_float2(a[2] + add0, a[3] + add1);
            }
        }
        __syncthreads();   // reads of buf (c&1) done before iter c+1 prefetches into it
    }
}

// ---- kernel 2: per-edge combine (memory-bound) ----------------------------------
__global__ void __launch_bounds__(256)
edge_kernel(const void* __restrict__ edges, const float* __restrict__ W2,
            const float* __restrict__ b2, float* __restrict__ out,
            int n_edges, int n_nodes)
{
    const int e = (blockIdx.x * blockDim.x + threadIdx.x) >> 5;
    const int lane = threadIdx.x & 31;
    if (e >= n_edges) return;

    int e0, e1;
    if (g_edges_is_i32) {
        const int* p = (const int*)edges;
        e0 = p[e]; e1 = p[n_edges + e];
    } else {
        const long long* p = (const long long*)edges;
        e0 = (int)p[e]; e1 = (int)p[n_edges + e];
    }
    if ((unsigned)e0 >= (unsigned)n_nodes) e0 = 0;
    if ((unsigned)e1 >= (unsigned)n_nodes) e1 = 0;

    const float4* u = reinterpret_cast<const float4*>(g_U + (size_t)e0 * 512);
    const float4* v = reinterpret_cast<const float4*>(g_V + (size_t)e1 * 512);

    float o0 = 0.f, o1 = 0.f;
    #pragma unroll
    for (int j = 0; j < 4; ++j) {
        const int idx = lane + 32 * j;                  // float4 index (coalesced)
        const float4 a = __ldg(u + idx);
        const float4 b = __ldg(v + idx);
        const float h0 = fmaxf(a.x + b.x, 0.f);
        const float h1 = fmaxf(a.y + b.y, 0.f);
        const float h2 = fmaxf(a.z + b.z, 0.f);
        const float h3 = fmaxf(a.w + b.w, 0.f);
        const int n = idx * 4;
        const float4 w0 = __ldg(reinterpret_cast<const float4*>(W2 + 2 * n));
        const float4 w1 = __ldg(reinterpret_cast<const float4*>(W2 + 2 * n + 4));
        o0 = fmaf(h0, w0.x, o0); o1 = fmaf(h0, w0.y, o1);
        o0 = fmaf(h1, w0.z, o0); o1 = fmaf(h1, w0.w, o1);
        o0 = fmaf(h2, w1.x, o0); o1 = fmaf(h2, w1.y, o1);
        o0 = fmaf(h3, w1.z, o0); o1 = fmaf(h3, w1.w, o1);
    }
    #pragma unroll
    for (int s = 16; s; s >>= 1) {
        o0 += __shfl_xor_sync(~0u, o0, s);
        o1 += __shfl_xor_sync(~0u, o1, s);
    }
    if (lane == 0) {
        *reinterpret_cast<float2*>(out + (size_t)e * 2) =
            make_float2(o0 + __ldg(&b2[0]), o1 + __ldg(&b2[1]));
    }
}

// ---- launcher -------------------------------------------------------------------
extern "C" void kernel_launch(void* const* d_in, const int* in_sizes, int n_in,
                              void* d_out, int out_size)
{
    const float* feat = nullptr; const void* edges = nullptr;
    const float* W1 = nullptr; const float* b1 = nullptr;
    const float* W2 = nullptr; const float* b2 = nullptr;
    int feat_elems = 12800000;

    for (int i = 0; i < n_in; ++i) {
        switch (in_sizes[i]) {
            case 12800000: feat = (const float*)d_in[i]; feat_elems = in_sizes[i]; break;
            case 1000000:  edges = d_in[i];               break;
            case 131072:   W1 = (const float*)d_in[i];    break;
            case 512:      b1 = (const float*)d_in[i];    break;
            case 1024:     W2 = (const float*)d_in[i];    break;
            case 2:        b2 = (const float*)d_in[i];    break;
            default: break;
        }
    }
    if (!feat  && n_in > 0) feat  = (const float*)d_in[0];
    if (!edges && n_in > 1) edges = d_in[1];
    if (!W1    && n_in > 2) W1    = (const float*)d_in[2];
    if (!b1    && n_in > 3) b1    = (const float*)d_in[3];
    if (!W2    && n_in > 4) W2    = (const float*)d_in[4];
    if (!b2    && n_in > 5) b2    = (const float*)d_in[5];

    const int n_edges = out_size / 2;
    int n_nodes = feat_elems / 128;
    if (n_nodes > NODES_MAX) n_nodes = NODES_MAX;

    const int n_check = n_edges < 4096 ? n_edges : 4096;
    detect_edge_dtype<<<1, 256>>>(edges, n_check, (long long)n_nodes);
    split_w1<<<512, 256>>>(W1);

    cudaFuncSetAttribute(uv_gemm_kernel,
                         cudaFuncAttributeMaxDynamicSharedMemorySize, SMEM_TOTAL);

    const int n_tiles = (n_nodes + 127) >> 7;
    uv_gemm_kernel<<<n_tiles, 256, SMEM_TOTAL>>>(feat, b1, n_nodes);

    const int eblocks = (n_edges * 32 + 255) / 256;
    edge_kernel<<<eblocks, 256>>>(edges, W2, b2, (float*)d_out, n_edges, n_nodes);
}

// round 17
// speedup vs baseline: 1.0016x; 1.0016x over previous
#include <cuda_runtime.h>
#include <cuda_bf16.h>
#include <cstdint>

// ============================================================================
// LinkPrediction, factored:
//   U = relu(x)@W1[0:128] + b1   (per node)     V = relu(x)@W1[128:256]
//   out[e] = relu(U[e0]+V[e1]) @ W2 + b2        (per edge, memory-bound)
// GEMM via warp-level bf16 hi/lo 3-term mma.sync (plain sm_103 compatible).
// ============================================================================

constexpr int NODES_MAX = 100352;          // 784 * 128
constexpr int KH   = 128;                  // feature dim
constexpr int NOUT = 1024;                 // 512 (U) + 512 (V) columns
constexpr int KPAD = 136;                  // padded k stride (bf16 elems) -> conflict-free ldmatrix

__device__ __nv_bfloat16 g_bp_hi[NOUT * KH];   // B' [n'][k] hi  (n'<512 -> W1_top^T, else W1_bot^T)
__device__ __nv_bfloat16 g_bp_lo[NOUT * KH];
__device__ float g_U[(size_t)NODES_MAX * 512];
__device__ float g_V[(size_t)NODES_MAX * 512];
__device__ int g_edges_is_i32;

// SMEM (bytes) for uv_gemm
constexpr int SA_HI = 0;                        // A hi [128][136] bf16 = 34816
constexpr int SA_LO = 34816;
constexpr int SB    = 69632;                    // 4 x [64][136] bf16 (2 stages x hi/lo)
constexpr int SB_SZ = 64 * KPAD * 2;            // 17408
constexpr int SMEM_TOTAL = SB + 4 * SB_SZ;      // 139264

__device__ __forceinline__ uint32_t smem_u32(const void* p) {
    uint32_t a;
    asm("{ .reg .u64 t; cvta.to.shared.u64 t, %1; cvt.u32.u64 %0, t; }" : "=r"(a) : "l"(p));
    return a;
}

#define LDSM_X4(r, addr) \
    asm volatile("ldmatrix.sync.aligned.m8n8.x4.shared.b16 {%0,%1,%2,%3}, [%4];" \
        : "=r"((r)[0]), "=r"((r)[1]), "=r"((r)[2]), "=r"((r)[3]) : "r"(addr))

#define MMA_BF16(d, a, b0_, b1_) \
    asm volatile("mma.sync.aligned.m16n8k16.row.col.f32.bf16.bf16.f32 " \
        "{%0,%1,%2,%3}, {%4,%5,%6,%7}, {%8,%9}, {%0,%1,%2,%3};" \
        : "+f"((d)[0]), "+f"((d)[1]), "+f"((d)[2]), "+f"((d)[3]) \
        : "r"((a)[0]), "r"((a)[1]), "r"((a)[2]), "r"((a)[3]), "r"(b0_), "r"(b1_))

__device__ __forceinline__ uint32_t split_pack(float x0, float x1, uint32_t& lo_pack) {
    __nv_bfloat16 h0 = __float2bfloat16(x0);
    __nv_bfloat16 h1 = __float2bfloat16(x1);
    __nv_bfloat16 l0 = __float2bfloat16(x0 - __bfloat162float(h0));
    __nv_bfloat16 l1 = __float2bfloat16(x1 - __bfloat162float(h1));
    lo_pack = (uint32_t)__bfloat16_as_ushort(l0) | ((uint32_t)__bfloat16_as_ushort(l1) << 16);
    return (uint32_t)__bfloat16_as_ushort(h0) | ((uint32_t)__bfloat16_as_ushort(h1) << 16);
}

// ---- prekernels -------------------------------------------------------------
__global__ void detect_edge_dtype(const void* __restrict__ edges, int n_check,
                                  long long n_nodes) {
    __shared__ int bad;
    if (threadIdx.x == 0) bad = 0;
    __syncthreads();
    const unsigned long long* e = (const unsigned long long*)edges;
    int local = 0;
    for (int i = threadIdx.x; i < n_check; i += blockDim.x)
        if (e[i] >= (unsigned long long)n_nodes) local = 1;
    if (local) bad = 1;
    __syncthreads();
    if (threadIdx.x == 0) g_edges_is_i32 = bad;
}

// W1 [256,512] -> B' [1024][128] hi/lo:  B'[n + 512*(k>>7)][k&127] = W1[k][n]
__global__ void split_w1(const float* __restrict__ W1) {
    int idx = blockIdx.x * blockDim.x + threadIdx.x;
    if (idx < 256 * 512) {
        int k = idx >> 9, n = idx & 511;
        float x = W1[idx];
        __nv_bfloat16 h = __float2bfloat16(x);
        int np = n + ((k >> 7) << 9);
        int kp = k & 127;
        g_bp_hi[np * KH + kp] = h;
        g_bp_lo[np * KH + kp] = __float2bfloat16(x - __bfloat162float(h));
    }
}

// ---- kernel 1: U/V GEMM -------------------------------------------------------
__device__ __forceinline__ void prefetch_b(uint32_t sb, int buf, int chunk, int tid) {
    #pragma unroll
    for (int v = 0; v < 2; ++v) {
        const __nv_bfloat16* src = v ? g_bp_lo : g_bp_hi;
        const uint32_t dst0 = sb + SB + (uint32_t)(buf * 2 + v) * SB_SZ;
        #pragma unroll
        for (int i = tid; i < 1024; i += 256) {          // 64 rows x 16 segs of 16B
            const int row = i >> 4, seg = i & 15;
            const uint32_t d = dst0 + (uint32_t)row * (KPAD * 2) + seg * 16;
            const void* s = src + (size_t)(chunk * 64 + row) * KH + seg * 8;
            asm volatile("cp.async.cg.shared.global [%0], [%1], 16;" :: "r"(d), "l"(s));
        }
    }
    asm volatile("cp.async.commit_group;");
}

__global__ void __launch_bounds__(256, 1)
uv_gemm_kernel(const float* __restrict__ feat, const float* __restrict__ b1,
               int n_nodes)
{
    extern __shared__ char smem[];
    const uint32_t sb = smem_u32(smem);
    const int tid = threadIdx.x, lane = tid & 31, wid = tid >> 5;
    const int m0 = blockIdx.x * 128;

    prefetch_b(sb, 0, 0, tid);

    // ---- A: 128 node rows, relu + bf16 hi/lo split (dense, coalesced) ----
    #pragma unroll 4
    for (int it = 0; it < 16; ++it) {
        const int r = it * 8 + wid;
        int node = m0 + r;
        if (node >= n_nodes) node = n_nodes - 1;
        float4 x = __ldg(reinterpret_cast<const float4*>(feat + (size_t)node * KH) + lane);
        x.x = fmaxf(x.x, 0.f); x.y = fmaxf(x.y, 0.f);
        x.z = fmaxf(x.z, 0.f); x.w = fmaxf(x.w, 0.f);
        uint32_t l01, l23;
        const uint32_t h01 = split_pack(x.x, x.y, l01);
        const uint32_t h23 = split_pack(x.z, x.w, l23);
        const uint32_t off = (uint32_t)(r * KPAD + lane * 4) * 2;
        *reinterpret_cast<uint2*>(smem + SA_HI + off) = make_uint2(h01, h23);
        *reinterpret_cast<uint2*>(smem + SA_LO + off) = make_uint2(l01, l23);
    }

    // warp tiling: 4 x 2 warps cover 128m x 64n per chunk; each warp 32m x 32n
    const int warpM = wid & 3, warpN = wid >> 2;
    const int lr = lane & 15;                  // ldmatrix row-within-16
    const int kq = (lane >> 4) * 8;            // ldmatrix k offset 0/8
    const uint32_t a_hi0 = sb + SA_HI + (uint32_t)((warpM * 32 + lr) * KPAD + kq) * 2;
    const uint32_t a_lo0 = sb + SA_LO + (uint32_t)((warpM * 32 + lr) * KPAD + kq) * 2;

    for (int c = 0; c < 16; ++c) {
        if (c + 1 < 16) {
            prefetch_b(sb, (c + 1) & 1, c + 1, tid);
            asm volatile("cp.async.wait_group 1;" ::: "memory");
        } else {
            asm volatile("cp.async.wait_group 0;" ::: "memory");
        }
        __syncthreads();   // B[c] (and A on first iter) visible

        const uint32_t bbase = sb + SB + (uint32_t)((c & 1) * 2) * SB_SZ;
        const uint32_t b_hi0 = bbase + (uint32_t)((warpN * 32 + lr) * KPAD + kq) * 2;
        const uint32_t b_lo0 = b_hi0 + SB_SZ;

        float acc[8][4];
        #pragma unroll
        for (int j = 0; j < 8; ++j)
            acc[j][0] = acc[j][1] = acc[j][2] = acc[j][3] = 0.f;

        #pragma unroll
        for (int k = 0; k < 128; k += 16) {
            uint32_t ah0[4], ah1[4], al0[4], al1[4];
            LDSM_X4(ah0, a_hi0 + k * 2);
            LDSM_X4(ah1, a_hi0 + (16 * KPAD + k) * 2);
            LDSM_X4(al0, a_lo0 + k * 2);
            LDSM_X4(al1, a_lo0 + (16 * KPAD + k) * 2);
            #pragma unroll
            for (int jj = 0; jj < 2; ++jj) {
                uint32_t bh[4], bl[4];
                LDSM_X4(bh, b_hi0 + (jj * 16 * KPAD + k) * 2);
                LDSM_X4(bl, b_lo0 + (jj * 16 * KPAD + k) * 2);
                // 3-term hi/lo split (lo*lo dropped)
                MMA_BF16(acc[jj * 2],     ah0, bh[0], bh[2]);
                MMA_BF16(acc[jj * 2 + 1], ah0, bh[1], bh[3]);
                MMA_BF16(acc[jj * 2],     ah0, bl[0], bl[2]);
                MMA_BF16(acc[jj * 2 + 1], ah0, bl[1], bl[3]);
                MMA_BF16(acc[jj * 2],     al0, bh[0], bh[2]);
                MMA_BF16(acc[jj * 2 + 1], al0, bh[1], bh[3]);
                MMA_BF16(acc[4 + jj * 2],     ah1, bh[0], bh[2]);
                MMA_BF16(acc[4 + jj * 2 + 1], ah1, bh[1], bh[3]);
                MMA_BF16(acc[4 + jj * 2],     ah1, bl[0], bl[2]);
                MMA_BF16(acc[4 + jj * 2 + 1], ah1, bl[1], bl[3]);
                MMA_BF16(acc[4 + jj * 2],     al1, bh[0], bh[2]);
                MMA_BF16(acc[4 + jj * 2 + 1], al1, bh[1], bh[3]);
            }
        }

        // ---- store D chunk straight to U / V (b1 folded into U) ----
        #pragma unroll
        for (int i = 0; i < 2; ++i) {
            #pragma unroll
            for (int j = 0; j < 4; ++j) {
                const float* a = acc[i * 4 + j];
                const int np = c * 64 + warpN * 32 + j * 8 + (lane & 3) * 2;
                const int mA = warpM * 32 + i * 16 + (lane >> 2);
                float add0 = 0.f, add1 = 0.f;
                float* base;
                if (np < 512) {
                    add0 = __ldg(&b1[np]); add1 = __ldg(&b1[np + 1]);
                    base = g_U + np;
                } else {
                    base = g_V + (np - 512);
                }
                const int n0 = m0 + mA, n1 = n0 + 8;
                if (n0 < n_nodes)
                    *reinterpret_cast<float2*>(base + (size_t)n0 * 512) =
                        make_float2(a[0] + add0, a[1] + add1);
                if (n1 < n_nodes)
                    *reinterpret_cast<float2*>(base + (size_t)n1 * 512) =
                        make_float2(a[2] + add0, a[3] + add1);
            }
        }
        __syncthreads();   // reads of buf (c&1) done before iter c+1 prefetches into it
    }
}

// ---- kernel 2: per-edge combine (memory-bound) ----------------------------------
__global__ void __launch_bounds__(256)
edge_kernel(const void* __restrict__ edges, const float* __restrict__ W2,
            const float* __restrict__ b2, float* __restrict__ out,
            int n_edges, int n_nodes)
{
    const int e = (blockIdx.x * blockDim.x + threadIdx.x) >> 5;
    const int lane = threadIdx.x & 31;
    if (e >= n_edges) return;

    int e0, e1;
    if (g_edges_is_i32) {
        const int* p = (const int*)edges;
        e0 = p[e]; e1 = p[n_edges + e];
    } else {
        const long long* p = (const long long*)edges;
        e0 = (int)p[e]; e1 = (int)p[n_edges + e];
    }
    if ((unsigned)e0 >= (unsigned)n_nodes) e0 = 0;
    if ((unsigned)e1 >= (unsigned)n_nodes) e1 = 0;

    const float4* u = reinterpret_cast<const float4*>(g_U + (size_t)e0 * 512);
    const float4* v = reinterpret_cast<const float4*>(g_V + (size_t)e1 * 512);

    float o0 = 0.f, o1 = 0.f;
    #pragma unroll
    for (int j = 0; j < 4; ++j) {
        const int idx = lane + 32 * j;                  // float4 index (coalesced)
        const float4 a = __ldg(u + idx);
        const float4 b = __ldg(v + idx);
        const float h0 = fmaxf(a.x + b.x, 0.f);
        const float h1 = fmaxf(a.y + b.y, 0.f);
        const float h2 = fmaxf(a.z + b.z, 0.f);
        const float h3 = fmaxf(a.w + b.w, 0.f);
        const int n = idx * 4;
        const float4 w0 = __ldg(reinterpret_cast<const float4*>(W2 + 2 * n));
        const float4 w1 = __ldg(reinterpret_cast<const float4*>(W2 + 2 * n + 4));
        o0 = fmaf(h0, w0.x, o0); o1 = fmaf(h0, w0.y, o1);
        o0 = fmaf(h1, w0.z, o0); o1 = fmaf(h1, w0.w, o1);
        o0 = fmaf(h2, w1.x, o0); o1 = fmaf(h2, w1.y, o1);
        o0 = fmaf(h3, w1.z, o0); o1 = fmaf(h3, w1.w, o1);
    }
    #pragma unroll
    for (int s = 16; s; s >>= 1) {
        o0 += __shfl_xor_sync(~0u, o0, s);
        o1 += __shfl_xor_sync(~0u, o1, s);
    }
    if (lane == 0) {
        *reinterpret_cast<float2*>(out + (size_t)e * 2) =
            make_float2(o0 + __ldg(&b2[0]), o1 + __ldg(&b2[1]));
    }
}

// ---- launcher -------------------------------------------------------------------
extern "C" void kernel_launch(void* const* d_in, const int* in_sizes, int n_in,
                              void* d_out, int out_size)
{
    const float* feat = nullptr; const void* edges = nullptr;
    const float* W1 = nullptr; const float* b1 = nullptr;
    const float* W2 = nullptr; const float* b2 = nullptr;
    int feat_elems = 12800000;

    for (int i = 0; i < n_in; ++i) {
        switch (in_sizes[i]) {
            case 12800000: feat = (const float*)d_in[i]; feat_elems = in_sizes[i]; break;
            case 1000000:  edges = d_in[i];               break;
            case 131072:   W1 = (const float*)d_in[i];    break;
            case 512:      b1 = (const float*)d_in[i];    break;
            case 1024:     W2 = (const float*)d_in[i];    break;
            case 2:        b2 = (const float*)d_in[i];    break;
            default: break;
        }
    }
    if (!feat  && n_in > 0) feat  = (const float*)d_in[0];
    if (!edges && n_in > 1) edges = d_in[1];
    if (!W1    && n_in > 2) W1    = (const float*)d_in[2];
    if (!b1    && n_in > 3) b1    = (const float*)d_in[3];
    if (!W2    && n_in > 4) W2    = (const float*)d_in[4];
    if (!b2    && n_in > 5) b2    = (const float*)d_in[5];

    const int n_edges = out_size / 2;
    int n_nodes = feat_elems / 128;
    if (n_nodes > NODES_MAX) n_nodes = NODES_MAX;

    const int n_check = n_edges < 4096 ? n_edges : 4096;
    detect_edge_dtype<<<1, 256>>>(edges, n_check, (long long)n_nodes);
    split_w1<<<512, 256>>>(W1);

    cudaFuncSetAttribute(uv_gemm_kernel,
                         cudaFuncAttributeMaxDynamicSharedMemorySize, SMEM_TOTAL);

    const int n_tiles = (n_nodes + 127) >> 7;
    uv_gemm_kernel<<<n_tiles, 256, SMEM_TOTAL>>>(feat, b1, n_nodes);

    const int eblocks = (n_edges * 32 + 255) / 256;
    edge_kernel<<<eblocks, 256>>>(edges, W2, b2, (float*)d_out, n_edges, n_nodes);
}